// round 10
// baseline (speedup 1.0000x reference)
#include <cuda_runtime.h>
#include <cstdint>

#define E_TOT  43234
#define ET     4
#define NWTILE 10809           // ceil(E_TOT/4)
#define NBLK   444             // 3 CTA/SM * 148
#define NTHR   256

// Rotated+NEGATED head, lane-transposed: g_head[dp*32 + b] = {-re(2dp),-re(2dp+1),-im(2dp),-im(2dp+1)}
__device__ float4 g_head[128 * 32];
__device__ int g_ctr;

// ---------- f32x2 packed helpers (sm_103a) ----------
static __device__ __forceinline__ unsigned long long addx2(unsigned long long a, unsigned long long b) {
    unsigned long long r; asm("add.rn.f32x2 %0, %1, %2;" : "=l"(r) : "l"(a), "l"(b)); return r;
}
static __device__ __forceinline__ unsigned long long mulx2(unsigned long long a, unsigned long long b) {
    unsigned long long r; asm("mul.rn.f32x2 %0, %1, %2;" : "=l"(r) : "l"(a), "l"(b)); return r;
}
static __device__ __forceinline__ unsigned long long fmax2(unsigned long long a, unsigned long long b, unsigned long long c) {
    unsigned long long r; asm("fma.rn.f32x2 %0, %1, %2, %3;" : "=l"(r) : "l"(a), "l"(b), "l"(c)); return r;
}
static __device__ __forceinline__ void unpack2(unsigned long long v, float& lo, float& hi) {
    asm("mov.b64 {%0, %1}, %2;" : "=f"(lo), "=f"(hi) : "l"(v));
}
static __device__ __forceinline__ float sqrt_approx(float x) {
    float r; asm("sqrt.approx.f32 %0, %1;" : "=f"(r) : "f"(x)); return r;
}

// ---------- prep: rotate head, negate + transpose; reset steal counter ----------
__global__ void prep_kernel(const float* __restrict__ head, const float* __restrict__ rel) {
    int b = blockIdx.x, d = threadIdx.x;
    if (b == 0 && d == 0) g_ctr = 0;
    float re_h = head[b * 512 + d];
    float im_h = head[b * 512 + 256 + d];
    float phase = rel[b * 256 + d] * 100.53096491487338f;  // rel * 32*pi
    float s, c; sincosf(phase, &s, &c);
    float re_rot = re_h * c - im_h * s;
    float im_rot = re_h * s + im_h * c;
    int dp = d >> 1, k = d & 1;
    float* base = reinterpret_cast<float*>(&g_head[dp * 32 + b]);
    base[k]     = -re_rot;
    base[2 + k] = -im_rot;
}

// ---------- main: lane = b, warp = 4-entity tile (work-stealing); 3 CTA/SM ----------
__global__ void __launch_bounds__(NTHR, 3)
dist_kernel(const float* __restrict__ ent, float* __restrict__ out) {
    extern __shared__ ulonglong2 sh2[];  // [128*32] = 64KB; sh2[dp*32+lane] = {re_pair, im_pair}
    {
        const float4* src = g_head;
        float4* dst = reinterpret_cast<float4*>(sh2);
        for (int i = threadIdx.x; i < 128 * 32; i += NTHR) dst[i] = src[i];
    }
    __syncthreads();

    const int lane = threadIdx.x & 31;
    const ulonglong2* __restrict__ hs = sh2 + lane;

    int tile;
    if (lane == 0) tile = atomicAdd(&g_ctr, 1);
    tile = __shfl_sync(0xffffffffu, tile, 0);

    while (tile < NWTILE) {
        int e0 = tile * ET;
        if (e0 > E_TOT - ET) e0 = E_TOT - ET;   // clamped tail: overlap rewrites identical values
        const ulonglong2* __restrict__ base =
            reinterpret_cast<const ulonglong2*>(ent) + (size_t)e0 * 128;
        // entity t: re quad = base[t*128 + q], im quad = base[t*128 + 64 + q]

        // grab next tile early (atomic latency hidden under the q-loop)
        int ntile;
        if (lane == 0) ntile = atomicAdd(&g_ctr, 1);
        ntile = __shfl_sync(0xffffffffu, ntile, 0);

        float acc0 = 0.0f, acc1 = 0.0f, acc2 = 0.0f, acc3 = 0.0f;

        for (int q = 0; q < 64; q++) {
            // 8 warp-uniform broadcast LDG.128 (consecutive q share 128B lines -> L1 hits)
            ulonglong2 re0 = __ldg(base + q);
            ulonglong2 im0 = __ldg(base + 64 + q);
            ulonglong2 re1 = __ldg(base + 128 + q);
            ulonglong2 im1 = __ldg(base + 192 + q);
            ulonglong2 re2 = __ldg(base + 256 + q);
            ulonglong2 im2 = __ldg(base + 320 + q);
            ulonglong2 re3 = __ldg(base + 384 + q);
            ulonglong2 im3 = __ldg(base + 448 + q);
            // this lane's head quads for d=4q..4q+3 (two conflict-free LDS.128)
            ulonglong2 h0 = hs[(2 * q) * 32];       // {-re pair d0d1, -im pair d0d1}
            ulonglong2 h1 = hs[(2 * q) * 32 + 32];  // {-re pair d2d3, -im pair d2d3}

            float x0, x1, y0, y1;
            unsigned long long a, c, p0, p1;

            a = addx2(re0.x, h0.x); c = addx2(im0.x, h0.y); p0 = fmax2(c, c, mulx2(a, a));
            a = addx2(re0.y, h1.x); c = addx2(im0.y, h1.y); p1 = fmax2(c, c, mulx2(a, a));
            unpack2(p0, x0, x1); unpack2(p1, y0, y1);
            acc0 += (sqrt_approx(x0) + sqrt_approx(x1)) + (sqrt_approx(y0) + sqrt_approx(y1));

            a = addx2(re1.x, h0.x); c = addx2(im1.x, h0.y); p0 = fmax2(c, c, mulx2(a, a));
            a = addx2(re1.y, h1.x); c = addx2(im1.y, h1.y); p1 = fmax2(c, c, mulx2(a, a));
            unpack2(p0, x0, x1); unpack2(p1, y0, y1);
            acc1 += (sqrt_approx(x0) + sqrt_approx(x1)) + (sqrt_approx(y0) + sqrt_approx(y1));

            a = addx2(re2.x, h0.x); c = addx2(im2.x, h0.y); p0 = fmax2(c, c, mulx2(a, a));
            a = addx2(re2.y, h1.x); c = addx2(im2.y, h1.y); p1 = fmax2(c, c, mulx2(a, a));
            unpack2(p0, x0, x1); unpack2(p1, y0, y1);
            acc2 += (sqrt_approx(x0) + sqrt_approx(x1)) + (sqrt_approx(y0) + sqrt_approx(y1));

            a = addx2(re3.x, h0.x); c = addx2(im3.x, h0.y); p0 = fmax2(c, c, mulx2(a, a));
            a = addx2(re3.y, h1.x); c = addx2(im3.y, h1.y); p1 = fmax2(c, c, mulx2(a, a));
            unpack2(p0, x0, x1); unpack2(p1, y0, y1);
            acc3 += (sqrt_approx(x0) + sqrt_approx(x1)) + (sqrt_approx(y0) + sqrt_approx(y1));
        }

        float2* op = reinterpret_cast<float2*>(out + (size_t)lane * E_TOT + e0);
        op[0] = make_float2(6.0f - acc0, 6.0f - acc1);
        op[1] = make_float2(6.0f - acc2, 6.0f - acc3);

        tile = ntile;
    }
}

extern "C" void kernel_launch(void* const* d_in, const int* in_sizes, int n_in,
                              void* d_out, int out_size) {
    const float* head = (const float*)d_in[0];   // (32, 512)
    const float* rel  = (const float*)d_in[1];   // (32, 256)
    const float* ent  = (const float*)d_in[2];   // (43234, 512)
    float* out = (float*)d_out;                  // (32, 43234)

    cudaFuncSetAttribute(dist_kernel, cudaFuncAttributeMaxDynamicSharedMemorySize, 65536);

    prep_kernel<<<32, 256>>>(head, rel);
    dist_kernel<<<NBLK, NTHR, 65536>>>(ent, out);
}

// round 11
// speedup vs baseline: 1.0452x; 1.0452x over previous
#include <cuda_runtime.h>
#include <cstdint>

#define E_TOT  43234
#define ET     4
#define NWTILE 10809           // ceil(E_TOT/4)
#define NBLK   296             // 2 CTA/SM * 148
#define NTHR   256

// Rotated+NEGATED head, lane-transposed: g_head[dp*32 + b] = {-re(2dp),-re(2dp+1),-im(2dp),-im(2dp+1)}
__device__ float4 g_head[128 * 32];
__device__ int g_ctr;

// ---------- f32x2 packed helpers (sm_103a) ----------
static __device__ __forceinline__ unsigned long long addx2(unsigned long long a, unsigned long long b) {
    unsigned long long r; asm("add.rn.f32x2 %0, %1, %2;" : "=l"(r) : "l"(a), "l"(b)); return r;
}
static __device__ __forceinline__ unsigned long long mulx2(unsigned long long a, unsigned long long b) {
    unsigned long long r; asm("mul.rn.f32x2 %0, %1, %2;" : "=l"(r) : "l"(a), "l"(b)); return r;
}
static __device__ __forceinline__ unsigned long long fmax2(unsigned long long a, unsigned long long b, unsigned long long c) {
    unsigned long long r; asm("fma.rn.f32x2 %0, %1, %2, %3;" : "=l"(r) : "l"(a), "l"(b), "l"(c)); return r;
}
static __device__ __forceinline__ void unpack2(unsigned long long v, float& lo, float& hi) {
    asm("mov.b64 {%0, %1}, %2;" : "=f"(lo), "=f"(hi) : "l"(v));
}
static __device__ __forceinline__ float sqrt_approx(float x) {
    float r; asm("sqrt.approx.f32 %0, %1;" : "=f"(r) : "f"(x)); return r;
}
// 256-bit broadcast load (sm_100+): 8 floats -> 4 f32x2-ready b64 pairs
static __device__ __forceinline__ void ldg256(const void* p, unsigned long long& p0,
                                              unsigned long long& p1, unsigned long long& p2,
                                              unsigned long long& p3) {
    asm("{\n\t"
        ".reg .f32 a<8>;\n\t"
        "ld.global.nc.v8.f32 {a0,a1,a2,a3,a4,a5,a6,a7}, [%4];\n\t"
        "mov.b64 %0, {a0,a1};\n\t"
        "mov.b64 %1, {a2,a3};\n\t"
        "mov.b64 %2, {a4,a5};\n\t"
        "mov.b64 %3, {a6,a7};\n\t"
        "}"
        : "=l"(p0), "=l"(p1), "=l"(p2), "=l"(p3) : "l"(p));
}

// ---------- prep: rotate head, negate + transpose; reset steal counter ----------
__global__ void prep_kernel(const float* __restrict__ head, const float* __restrict__ rel) {
    int b = blockIdx.x, d = threadIdx.x;
    if (b == 0 && d == 0) g_ctr = 0;
    float re_h = head[b * 512 + d];
    float im_h = head[b * 512 + 256 + d];
    float phase = rel[b * 256 + d] * 100.53096491487338f;  // rel * 32*pi
    float s, c; sincosf(phase, &s, &c);
    float re_rot = re_h * c - im_h * s;
    float im_rot = re_h * s + im_h * c;
    int dp = d >> 1, k = d & 1;
    float* base = reinterpret_cast<float*>(&g_head[dp * 32 + b]);
    base[k]     = -re_rot;
    base[2 + k] = -im_rot;
}

// ---------- main: lane = b, warp = 4-entity tile, 256-bit entity loads, work stealing ----------
__global__ void __launch_bounds__(NTHR, 2)
dist_kernel(const float* __restrict__ ent, float* __restrict__ out) {
    extern __shared__ ulonglong2 sh2[];  // [128*32] = 64KB; sh2[dp*32+lane] = {re_pair, im_pair}
    {
        const float4* src = g_head;
        float4* dst = reinterpret_cast<float4*>(sh2);
        for (int i = threadIdx.x; i < 128 * 32; i += NTHR) dst[i] = src[i];
    }
    __syncthreads();

    const int lane = threadIdx.x & 31;
    const ulonglong2* __restrict__ hs = sh2 + lane;

    int tile;
    if (lane == 0) tile = atomicAdd(&g_ctr, 1);
    tile = __shfl_sync(0xffffffffu, tile, 0);

    while (tile < NWTILE) {
        int e0 = tile * ET;
        if (e0 > E_TOT - ET) e0 = E_TOT - ET;   // clamped tail: overlap rewrites identical values
        const char* ebase = reinterpret_cast<const char*>(ent) + (size_t)e0 * 2048;
        // entity t: re 32B-chunks at +t*2048 + qp*32; im at +t*2048 + 1024 + qp*32

        // grab next tile early (atomic latency hidden under the qp-loop)
        int ntile;
        if (lane == 0) ntile = atomicAdd(&g_ctr, 1);
        ntile = __shfl_sync(0xffffffffu, ntile, 0);

        float acc0 = 0.0f, acc1 = 0.0f, acc2 = 0.0f, acc3 = 0.0f;

#pragma unroll 2
        for (int qp = 0; qp < 32; qp++) {        // qp covers q = 2qp, 2qp+1 (8 d-values)
            // 8 × LDG.256 broadcast: 4 f32x2 pairs each
            unsigned long long r0a, r0b, r0c, r0d, i0a, i0b, i0c, i0d;
            unsigned long long r1a, r1b, r1c, r1d, i1a, i1b, i1c, i1d;
            unsigned long long r2a, r2b, r2c, r2d, i2a, i2b, i2c, i2d;
            unsigned long long r3a, r3b, r3c, r3d, i3a, i3b, i3c, i3d;
            ldg256(ebase + qp * 32,               r0a, r0b, r0c, r0d);
            ldg256(ebase + 1024 + qp * 32,        i0a, i0b, i0c, i0d);
            ldg256(ebase + 2048 + qp * 32,        r1a, r1b, r1c, r1d);
            ldg256(ebase + 3072 + qp * 32,        i1a, i1b, i1c, i1d);
            ldg256(ebase + 4096 + qp * 32,        r2a, r2b, r2c, r2d);
            ldg256(ebase + 5120 + qp * 32,        i2a, i2b, i2c, i2d);
            ldg256(ebase + 6144 + qp * 32,        r3a, r3b, r3c, r3d);
            ldg256(ebase + 7168 + qp * 32,        i3a, i3b, i3c, i3d);

            // this lane's head quads: 4 × LDS.128 for dp = 4qp .. 4qp+3
            ulonglong2 h0 = hs[(4 * qp) * 32];          // {re pair, im pair} dp0
            ulonglong2 h1 = hs[(4 * qp + 1) * 32];
            ulonglong2 h2 = hs[(4 * qp + 2) * 32];
            ulonglong2 h3 = hs[(4 * qp + 3) * 32];

            float x0, x1, y0, y1;
            unsigned long long a, c, p0, p1;

#define DO_ENT(ACC, RA, RB, RC, RD, IA, IB, IC, ID)                                   \
            a = addx2(RA, h0.x); c = addx2(IA, h0.y); p0 = fmax2(c, c, mulx2(a, a));  \
            a = addx2(RB, h1.x); c = addx2(IB, h1.y); p1 = fmax2(c, c, mulx2(a, a));  \
            unpack2(p0, x0, x1); unpack2(p1, y0, y1);                                 \
            ACC += (sqrt_approx(x0) + sqrt_approx(x1)) + (sqrt_approx(y0) + sqrt_approx(y1)); \
            a = addx2(RC, h2.x); c = addx2(IC, h2.y); p0 = fmax2(c, c, mulx2(a, a));  \
            a = addx2(RD, h3.x); c = addx2(ID, h3.y); p1 = fmax2(c, c, mulx2(a, a));  \
            unpack2(p0, x0, x1); unpack2(p1, y0, y1);                                 \
            ACC += (sqrt_approx(x0) + sqrt_approx(x1)) + (sqrt_approx(y0) + sqrt_approx(y1));

            DO_ENT(acc0, r0a, r0b, r0c, r0d, i0a, i0b, i0c, i0d)
            DO_ENT(acc1, r1a, r1b, r1c, r1d, i1a, i1b, i1c, i1d)
            DO_ENT(acc2, r2a, r2b, r2c, r2d, i2a, i2b, i2c, i2d)
            DO_ENT(acc3, r3a, r3b, r3c, r3d, i3a, i3b, i3c, i3d)
#undef DO_ENT
        }

        float2* op = reinterpret_cast<float2*>(out + (size_t)lane * E_TOT + e0);
        op[0] = make_float2(6.0f - acc0, 6.0f - acc1);
        op[1] = make_float2(6.0f - acc2, 6.0f - acc3);

        tile = ntile;
    }
}

extern "C" void kernel_launch(void* const* d_in, const int* in_sizes, int n_in,
                              void* d_out, int out_size) {
    const float* head = (const float*)d_in[0];   // (32, 512)
    const float* rel  = (const float*)d_in[1];   // (32, 256)
    const float* ent  = (const float*)d_in[2];   // (43234, 512)
    float* out = (float*)d_out;                  // (32, 43234)

    cudaFuncSetAttribute(dist_kernel, cudaFuncAttributeMaxDynamicSharedMemorySize, 65536);

    prep_kernel<<<32, 256>>>(head, rel);
    dist_kernel<<<NBLK, NTHR, 65536>>>(ent, out);
}

// round 12
// speedup vs baseline: 1.2092x; 1.1569x over previous
#include <cuda_runtime.h>
#include <cstdint>

#define E_TOT  43234
#define ET     4
#define NWTILE 10809           // ceil(E_TOT/4)
#define NBLK   296             // 2 CTA/SM * 148
#define NTHR   256

// Rotated+NEGATED head, lane-transposed: g_head[dp*32 + b] = {-re(2dp),-re(2dp+1),-im(2dp),-im(2dp+1)}
__device__ float4 g_head[128 * 32];
__device__ int g_ctr;

// ---------- f32x2 packed helpers (sm_103a) ----------
static __device__ __forceinline__ unsigned long long addx2(unsigned long long a, unsigned long long b) {
    unsigned long long r; asm("add.rn.f32x2 %0, %1, %2;" : "=l"(r) : "l"(a), "l"(b)); return r;
}
static __device__ __forceinline__ unsigned long long mulx2(unsigned long long a, unsigned long long b) {
    unsigned long long r; asm("mul.rn.f32x2 %0, %1, %2;" : "=l"(r) : "l"(a), "l"(b)); return r;
}
static __device__ __forceinline__ unsigned long long fmax2(unsigned long long a, unsigned long long b, unsigned long long c) {
    unsigned long long r; asm("fma.rn.f32x2 %0, %1, %2, %3;" : "=l"(r) : "l"(a), "l"(b), "l"(c)); return r;
}
static __device__ __forceinline__ void unpack2(unsigned long long v, float& lo, float& hi) {
    asm("mov.b64 {%0, %1}, %2;" : "=f"(lo), "=f"(hi) : "l"(v));
}
static __device__ __forceinline__ float sqrt_approx(float x) {
    float r; asm("sqrt.approx.f32 %0, %1;" : "=f"(r) : "f"(x)); return r;
}

// ---------- prep: rotate head, negate + transpose; reset steal counter ----------
__global__ void prep_kernel(const float* __restrict__ head, const float* __restrict__ rel) {
    int b = blockIdx.x, d = threadIdx.x;
    if (b == 0 && d == 0) g_ctr = 0;
    float re_h = head[b * 512 + d];
    float im_h = head[b * 512 + 256 + d];
    float phase = rel[b * 256 + d] * 100.53096491487338f;  // rel * 32*pi
    float s, c; sincosf(phase, &s, &c);
    float re_rot = re_h * c - im_h * s;
    float im_rot = re_h * s + im_h * c;
    int dp = d >> 1, k = d & 1;
    float* base = reinterpret_cast<float*>(&g_head[dp * 32 + b]);
    base[k]     = -re_rot;
    base[2 + k] = -im_rot;
}

// ---------- main: lane = b, warp = 4-entity tile; R3 pipelined body + work stealing ----------
__global__ void __launch_bounds__(NTHR, 2)
dist_kernel(const float* __restrict__ ent, float* __restrict__ out) {
    extern __shared__ ulonglong2 sh2[];  // [128*32] = 64KB; sh2[dp*32+lane] = {re_pair, im_pair}
    {
        const float4* src = g_head;
        float4* dst = reinterpret_cast<float4*>(sh2);
        for (int i = threadIdx.x; i < 128 * 32; i += NTHR) dst[i] = src[i];
    }
    __syncthreads();

    const int lane = threadIdx.x & 31;
    const ulonglong2* __restrict__ hs = sh2 + lane;

    int tile;
    if (lane == 0) tile = atomicAdd(&g_ctr, 1);
    tile = __shfl_sync(0xffffffffu, tile, 0);

    while (tile < NWTILE) {
        int e0 = tile * ET;
        if (e0 > E_TOT - ET) e0 = E_TOT - ET;   // clamped tail: overlap rewrites identical values
        const ulonglong2* __restrict__ base =
            reinterpret_cast<const ulonglong2*>(ent) + (size_t)e0 * 128;
        // entity t: re quad = base[t*128 + q], im quad = base[t*128 + 64 + q]

        // grab next tile early (atomic+shfl latency hidden under the q-loop)
        int ntile;
        if (lane == 0) ntile = atomicAdd(&g_ctr, 1);
        ntile = __shfl_sync(0xffffffffu, ntile, 0);

        float acc0[ET], acc1[ET];
#pragma unroll
        for (int t = 0; t < ET; t++) { acc0[t] = 0.0f; acc1[t] = 0.0f; }

        ulonglong2 cre[ET], cim[ET], nre[ET], nim[ET];
        ulonglong2 ch0, ch1, nh0, nh1;

        // prologue: q = 0
        ch0 = hs[0];
        ch1 = hs[32];
#pragma unroll
        for (int t = 0; t < ET; t++) {
            cre[t] = __ldg(base + t * 128);
            cim[t] = __ldg(base + t * 128 + 64);
        }

#pragma unroll 2
        for (int q = 0; q < 64; q++) {
            // prefetch q+1 (clamped to 0 on last iter: in-bounds, discarded)
            const int qn = (q + 1 < 64) ? (q + 1) : 0;
            nh0 = hs[(2 * qn) * 32];
            nh1 = hs[(2 * qn) * 32 + 32];
#pragma unroll
            for (int t = 0; t < ET; t++) {
                nre[t] = __ldg(base + t * 128 + qn);
                nim[t] = __ldg(base + t * 128 + 64 + qn);
            }

            // compute on current
#pragma unroll
            for (int t = 0; t < ET; t++) {
                unsigned long long a0 = addx2(cre[t].x, ch0.x);
                unsigned long long b0 = addx2(cim[t].x, ch0.y);
                unsigned long long a1 = addx2(cre[t].y, ch1.x);
                unsigned long long b1 = addx2(cim[t].y, ch1.y);
                unsigned long long p0 = fmax2(b0, b0, mulx2(a0, a0));
                unsigned long long p1 = fmax2(b1, b1, mulx2(a1, a1));
                float x0, x1, y0, y1;
                unpack2(p0, x0, x1);
                unpack2(p1, y0, y1);
                acc0[t] += sqrt_approx(x0) + sqrt_approx(y0);
                acc1[t] += sqrt_approx(x1) + sqrt_approx(y1);
            }

            // rotate buffers (renamed away by unroll 2)
            ch0 = nh0;
            ch1 = nh1;
#pragma unroll
            for (int t = 0; t < ET; t++) { cre[t] = nre[t]; cim[t] = nim[t]; }
        }

        float2* op = reinterpret_cast<float2*>(out + (size_t)lane * E_TOT + e0);
        op[0] = make_float2(6.0f - (acc0[0] + acc1[0]), 6.0f - (acc0[1] + acc1[1]));
        op[1] = make_float2(6.0f - (acc0[2] + acc1[2]), 6.0f - (acc0[3] + acc1[3]));

        tile = ntile;
    }
}

extern "C" void kernel_launch(void* const* d_in, const int* in_sizes, int n_in,
                              void* d_out, int out_size) {
    const float* head = (const float*)d_in[0];   // (32, 512)
    const float* rel  = (const float*)d_in[1];   // (32, 256)
    const float* ent  = (const float*)d_in[2];   // (43234, 512)
    float* out = (float*)d_out;                  // (32, 43234)

    cudaFuncSetAttribute(dist_kernel, cudaFuncAttributeMaxDynamicSharedMemorySize, 65536);

    prep_kernel<<<32, 256>>>(head, rel);
    dist_kernel<<<NBLK, NTHR, 65536>>>(ent, out);
}

// round 14
// speedup vs baseline: 1.3334x; 1.1027x over previous
#include <cuda_runtime.h>
#include <cstdint>

#define E_TOT  43234
#define ET     4
#define NWTILE 10809           // ceil(E_TOT/4)
#define NBLK   296             // 2 CTA/SM * 148
#define NTHR   256

// Rotated+NEGATED head, lane-transposed: g_head[dp*32 + b] = {-re(2dp),-re(2dp+1),-im(2dp),-im(2dp+1)}
__device__ float4 g_head[128 * 32];
__device__ int g_ctr;

// ---------- f32x2 packed helpers (sm_103a) ----------
static __device__ __forceinline__ unsigned long long addx2(unsigned long long a, unsigned long long b) {
    unsigned long long r; asm("add.rn.f32x2 %0, %1, %2;" : "=l"(r) : "l"(a), "l"(b)); return r;
}
static __device__ __forceinline__ unsigned long long mulx2(unsigned long long a, unsigned long long b) {
    unsigned long long r; asm("mul.rn.f32x2 %0, %1, %2;" : "=l"(r) : "l"(a), "l"(b)); return r;
}
static __device__ __forceinline__ unsigned long long fmax2(unsigned long long a, unsigned long long b, unsigned long long c) {
    unsigned long long r; asm("fma.rn.f32x2 %0, %1, %2, %3;" : "=l"(r) : "l"(a), "l"(b), "l"(c)); return r;
}
static __device__ __forceinline__ void unpack2(unsigned long long v, float& lo, float& hi) {
    asm("mov.b64 {%0, %1}, %2;" : "=f"(lo), "=f"(hi) : "l"(v));
}
static __device__ __forceinline__ float sqrt_approx(float x) {
    float r; asm("sqrt.approx.f32 %0, %1;" : "=f"(r) : "f"(x)); return r;
}

// ---------- prep: rotate head, negate + transpose; reset steal counter ----------
__global__ void prep_kernel(const float* __restrict__ head, const float* __restrict__ rel) {
    int b = blockIdx.x, d = threadIdx.x;
    if (b == 0 && d == 0) g_ctr = 0;
    float re_h = head[b * 512 + d];
    float im_h = head[b * 512 + 256 + d];
    float phase = rel[b * 256 + d] * 100.53096491487338f;  // rel * 32*pi
    float s, c; sincosf(phase, &s, &c);
    float re_rot = re_h * c - im_h * s;
    float im_rot = re_h * s + im_h * c;
    int dp = d >> 1, k = d & 1;
    float* base = reinterpret_cast<float*>(&g_head[dp * 32 + b]);
    base[k]     = -re_rot;
    base[2 + k] = -im_rot;
}

// ---------- main: lane = b, warp = 4-entity tile; entity staged via coalesced LDG+STS,
//            consumed via broadcast LDS; per-warp double buffer, no CTA barriers ----------
__global__ void __launch_bounds__(NTHR, 2)
dist_kernel(const float* __restrict__ ent, float* __restrict__ out) {
    extern __shared__ char smem[];
    // [0, 32768): 8 warps * (2 bufs * 2KB) entity stages
    // [32768, 98304): head table 64KB
    ulonglong2* Hs = reinterpret_cast<ulonglong2*>(smem + 32768);
    {
        const float4* src = g_head;
        float4* dst = reinterpret_cast<float4*>(Hs);
        for (int i = threadIdx.x; i < 4096; i += NTHR) dst[i] = src[i];
    }
    __syncthreads();

    const int lane = threadIdx.x & 31;
    const int wid  = threadIdx.x >> 5;
    char* wstage = smem + wid * 4096;                    // 2 bufs * 2KB
    const int foff = (lane >> 4) * 1024 + (lane & 15) * 16;   // gmem fill offset per lane
    const int soff = (lane >> 4) * 256 + (lane & 15) * 16;    // smem fill offset per lane
    const ulonglong2* __restrict__ hs = Hs + lane;

    int tile;
    if (lane == 0) tile = atomicAdd(&g_ctr, 1);
    tile = __shfl_sync(0xffffffffu, tile, 0);
    if (tile >= NWTILE) return;

    int e0 = tile * ET;
    if (e0 > E_TOT - ET) e0 = E_TOT - ET;
    const char* base = reinterpret_cast<const char*>(ent) + (size_t)e0 * 2048;

    // fill chunk 0 into buf 0:  4 coalesced LDG.128 + 4 STS.128
    uint4 g0, g1, g2, g3;
    {
        const char* a = base + foff;
        g0 = *reinterpret_cast<const uint4*>(a);
        g1 = *reinterpret_cast<const uint4*>(a + 2048);
        g2 = *reinterpret_cast<const uint4*>(a + 4096);
        g3 = *reinterpret_cast<const uint4*>(a + 6144);
        char* s = wstage + soff;
        *reinterpret_cast<uint4*>(s)        = g0;
        *reinterpret_cast<uint4*>(s + 512)  = g1;
        *reinterpret_cast<uint4*>(s + 1024) = g2;
        *reinterpret_cast<uint4*>(s + 1536) = g3;
    }
    __syncwarp();

    int cur = 0;
    while (true) {
        // grab next tile now (address needed for cross-tile chunk-0 prefetch)
        int ntile;
        if (lane == 0) ntile = atomicAdd(&g_ctr, 1);
        ntile = __shfl_sync(0xffffffffu, ntile, 0);
        int ne0 = (ntile < NWTILE) ? ntile * ET : 0;
        if (ne0 > E_TOT - ET) ne0 = E_TOT - ET;
        const char* nbase = reinterpret_cast<const char*>(ent) + (size_t)ne0 * 2048;

        float acc0[ET] = {0, 0, 0, 0}, acc1[ET] = {0, 0, 0, 0};

#pragma unroll
        for (int c = 0; c < 4; c++) {
            // issue fill LDGs for next chunk (or next tile's chunk 0) — consumed after compute
            const char* a = ((c < 3) ? (base + (c + 1) * 256) : nbase) + foff;
            g0 = *reinterpret_cast<const uint4*>(a);
            g1 = *reinterpret_cast<const uint4*>(a + 2048);
            g2 = *reinterpret_cast<const uint4*>(a + 4096);
            g3 = *reinterpret_cast<const uint4*>(a + 6144);

            // consume chunk c from buf cur: per q: 8 broadcast LDS + 2 per-lane head LDS
            const char* sb = wstage + cur * 2048;
#pragma unroll 4
            for (int qq = 0; qq < 16; qq++) {
                const int q = c * 16 + qq;
                ulonglong2 er[ET], ei[ET];
#pragma unroll
                for (int t = 0; t < ET; t++) {
                    er[t] = *reinterpret_cast<const ulonglong2*>(sb + t * 512 + qq * 16);
                    ei[t] = *reinterpret_cast<const ulonglong2*>(sb + t * 512 + 256 + qq * 16);
                }
                ulonglong2 h0 = hs[(2 * q) * 32];
                ulonglong2 h1 = hs[(2 * q) * 32 + 32];
#pragma unroll
                for (int t = 0; t < ET; t++) {
                    unsigned long long a0 = addx2(er[t].x, h0.x);
                    unsigned long long b0 = addx2(ei[t].x, h0.y);
                    unsigned long long a1 = addx2(er[t].y, h1.x);
                    unsigned long long b1 = addx2(ei[t].y, h1.y);
                    unsigned long long p0 = fmax2(b0, b0, mulx2(a0, a0));
                    unsigned long long p1 = fmax2(b1, b1, mulx2(a1, a1));
                    float x0, x1, y0, y1;
                    unpack2(p0, x0, x1);
                    unpack2(p1, y0, y1);
                    acc0[t] += sqrt_approx(x0) + sqrt_approx(y0);
                    acc1[t] += sqrt_approx(x1) + sqrt_approx(y1);
                }
            }

            // store fills into the other buffer, then sync the warp
            char* s = wstage + (cur ^ 1) * 2048 + soff;
            *reinterpret_cast<uint4*>(s)        = g0;
            *reinterpret_cast<uint4*>(s + 512)  = g1;
            *reinterpret_cast<uint4*>(s + 1024) = g2;
            *reinterpret_cast<uint4*>(s + 1536) = g3;
            __syncwarp();
            cur ^= 1;
        }

        float2* op = reinterpret_cast<float2*>(out + (size_t)lane * E_TOT + e0);
        op[0] = make_float2(6.0f - (acc0[0] + acc1[0]), 6.0f - (acc0[1] + acc1[1]));
        op[1] = make_float2(6.0f - (acc0[2] + acc1[2]), 6.0f - (acc0[3] + acc1[3]));

        if (ntile >= NWTILE) break;
        base = nbase;
        e0 = ne0;
    }
}

extern "C" void kernel_launch(void* const* d_in, const int* in_sizes, int n_in,
                              void* d_out, int out_size) {
    const float* head = (const float*)d_in[0];   // (32, 512)
    const float* rel  = (const float*)d_in[1];   // (32, 256)
    const float* ent  = (const float*)d_in[2];   // (43234, 512)
    float* out = (float*)d_out;                  // (32, 43234)

    cudaFuncSetAttribute(dist_kernel, cudaFuncAttributeMaxDynamicSharedMemorySize, 98304);

    prep_kernel<<<32, 256>>>(head, rel);
    dist_kernel<<<NBLK, NTHR, 98304>>>(ent, out);
}